// round 14
// baseline (speedup 1.0000x reference)
#include <cuda_runtime.h>
#include <cuda_bf16.h>
#include <math.h>
#include <stdint.h>

#define BSZ 2
#define SEQ 2048
#define NX 768
#define NH 12
#define HD 64
#define MROWS (BSZ*SEQ)      // 4096
#define NQKV (3*NX)          // 2304

// Scratch (no cudaMalloc allowed)
__device__ __nv_bfloat16 g_Qh[BSZ*NH*SEQ*HD];
__device__ __nv_bfloat16 g_Ql[BSZ*NH*SEQ*HD];
__device__ __nv_bfloat16 g_Kh[BSZ*NH*SEQ*HD];
__device__ __nv_bfloat16 g_Kl[BSZ*NH*SEQ*HD];
__device__ __nv_bfloat16 g_Vh[BSZ*NH*SEQ*HD];
__device__ __nv_bfloat16 g_Vl[BSZ*NH*SEQ*HD];
__device__ __nv_bfloat16 g_Ah[BSZ*SEQ*NX];   // attn out hi (feeds proj)
__device__ __nv_bfloat16 g_Al[BSZ*SEQ*NX];   // attn out lo
__device__ __nv_bfloat16 g_Bh1[NQKV*NX];     // w_attn^T hi  [2304][768]
__device__ __nv_bfloat16 g_Bl1[NQKV*NX];
__device__ __nv_bfloat16 g_Bh2[NX*NX];       // w_proj^T hi  [768][768]
__device__ __nv_bfloat16 g_Bl2[NX*NX];

// ---------------------------------------------------------------------------
// helpers
// ---------------------------------------------------------------------------
__device__ __forceinline__ uint32_t smem_u32(const void* p) {
    uint32_t a;
    asm("{ .reg .u64 t; cvta.to.shared.u64 t, %1; cvt.u32.u64 %0, t; }"
        : "=r"(a) : "l"(p));
    return a;
}
__device__ __forceinline__ void mma_bf16(float* d, const uint32_t* a, const uint32_t* b) {
    asm volatile(
        "mma.sync.aligned.m16n8k16.row.col.f32.bf16.bf16.f32 "
        "{%0,%1,%2,%3}, {%4,%5,%6,%7}, {%8,%9}, {%0,%1,%2,%3};"
        : "+f"(d[0]), "+f"(d[1]), "+f"(d[2]), "+f"(d[3])
        : "r"(a[0]), "r"(a[1]), "r"(a[2]), "r"(a[3]), "r"(b[0]), "r"(b[1]));
}
__device__ __forceinline__ void ldm_x4(uint32_t* r, uint32_t addr) {
    asm volatile("ldmatrix.sync.aligned.m8n8.x4.shared.b16 {%0,%1,%2,%3}, [%4];"
                 : "=r"(r[0]), "=r"(r[1]), "=r"(r[2]), "=r"(r[3]) : "r"(addr));
}
__device__ __forceinline__ void ldm_x2(uint32_t* r, uint32_t addr) {
    asm volatile("ldmatrix.sync.aligned.m8n8.x2.shared.b16 {%0,%1}, [%2];"
                 : "=r"(r[0]), "=r"(r[1]) : "r"(addr));
}
__device__ __forceinline__ void ldm_x4t(uint32_t* r, uint32_t addr) {
    asm volatile("ldmatrix.sync.aligned.m8n8.x4.trans.shared.b16 {%0,%1,%2,%3}, [%4];"
                 : "=r"(r[0]), "=r"(r[1]), "=r"(r[2]), "=r"(r[3]) : "r"(addr));
}
__device__ __forceinline__ void cp_async16(uint32_t dst, const void* src) {
    asm volatile("cp.async.cg.shared.global [%0], [%1], 16;"
                 :: "r"(dst), "l"(src) : "memory");
}
__device__ __forceinline__ void cp_commit() {
    asm volatile("cp.async.commit_group;" ::: "memory");
}
__device__ __forceinline__ void cp_wait0() {
    asm volatile("cp.async.wait_group 0;" ::: "memory");
}
__device__ __forceinline__ void cp_wait1() {
    asm volatile("cp.async.wait_group 1;" ::: "memory");
}
// split two fp32 into packed bf16 hi2 / lo2
__device__ __forceinline__ void split2(float a, float b, uint32_t& hi, uint32_t& lo) {
    __nv_bfloat16 ha = __float2bfloat16_rn(a), hb = __float2bfloat16_rn(b);
    __nv_bfloat16 la = __float2bfloat16_rn(a - __bfloat162float(ha));
    __nv_bfloat16 lb = __float2bfloat16_rn(b - __bfloat162float(hb));
    __nv_bfloat162 H(ha, hb), L(la, lb);
    hi = *(uint32_t*)&H; lo = *(uint32_t*)&L;
}

// ---------------------------------------------------------------------------
// Pre-pass 1: transpose + bf16-split weights.  B[K,N] fp32 -> Th/Tl [N][K]
// ---------------------------------------------------------------------------
__global__ void __launch_bounds__(256)
wsplitT(const float* __restrict__ B, __nv_bfloat16* __restrict__ Th,
        __nv_bfloat16* __restrict__ Tl, int K, int N)
{
    __shared__ float t[32][33];
    const int c  = threadIdx.x & 31;
    const int r4 = threadIdx.x >> 5;
    const int n0 = blockIdx.x * 32;
    const int k0 = blockIdx.y * 32;
#pragma unroll
    for (int i = 0; i < 4; i++)
        t[r4 + 8*i][c] = B[(size_t)(k0 + r4 + 8*i) * N + n0 + c];
    __syncthreads();
#pragma unroll
    for (int i = 0; i < 4; i++) {
        const int n = n0 + r4 + 8*i;
        const float v = t[c][r4 + 8*i];
        const __nv_bfloat16 hi = __float2bfloat16_rn(v);
        Th[(size_t)n * K + k0 + c] = hi;
        Tl[(size_t)n * K + k0 + c] = __float2bfloat16_rn(v - __bfloat162float(hi));
    }
}

// Pre-pass 2: elementwise bf16 split of activations
__global__ void __launch_bounds__(256)
asplit(const float* __restrict__ X, __nv_bfloat16* __restrict__ H,
       __nv_bfloat16* __restrict__ L)
{
    const size_t i = (size_t)blockIdx.x * 256 + threadIdx.x;
    float4 x = ((const float4*)X)[i];
    uint32_t h0, l0, h1, l1;
    split2(x.x, x.y, h0, l0);
    split2(x.z, x.w, h1, l1);
    ((uint32_t*)H)[2*i]   = h0;
    ((uint32_t*)H)[2*i+1] = h1;
    ((uint32_t*)L)[2*i]   = l0;
    ((uint32_t*)L)[2*i+1] = l1;
}

// ---------------------------------------------------------------------------
// HMMA bf16 3-product GEMM: C = A @ Bt^T + bias
// R14: 3-stage cp.async pipeline (prefetch distance 2, wait_group 1) +
// double-buffered A-fragment loads (ldm->MMA distance >= 12).
// Dynamic smem 72 KB (3 bufs x 4 arrays), 2 CTAs/SM (reg cap 128).
// MODE 1: writes Q/K/V bf16 hi/lo via the reference's QUIRKY direct reshape:
//         flat f = sq*768 + nn -> t = sq*NH + (nn>>6); h = t>>11; s2 = t&2047.
// MODE 0: fp32 C.
// ---------------------------------------------------------------------------
#define RP 24
#define GBUF (128*RP*2)      // 6144 bytes per buffer per array
#define GEMM_SMEM (12*GBUF)  // 3 bufs x 4 arrays = 73728 B
__global__ void __launch_bounds__(256, 2)
mma_gemm_impl(const __nv_bfloat16* __restrict__ Ahg, const __nv_bfloat16* __restrict__ Alg,
              const __nv_bfloat16* __restrict__ Bhg, const __nv_bfloat16* __restrict__ Blg,
              const float* __restrict__ bias, float* __restrict__ C,
              int N, int K, int MODE)
{
    extern __shared__ __nv_bfloat16 gsm[];

    const int tid  = threadIdx.x;
    const int wid  = tid >> 5;
    const int lane = tid & 31;
    const int wm   = wid >> 2;
    const int wn   = wid & 3;
    const int m0 = blockIdx.y * 128;
    const int n0 = blockIdx.x * 128;

    const uint32_t sb  = smem_u32(gsm);
    const uint32_t bAh = sb;
    const uint32_t bAl = sb + 3*GBUF;
    const uint32_t bBh = sb + 6*GBUF;
    const uint32_t bBl = sb + 9*GBUF;

    const int row  = tid >> 1;
    const int half = tid & 1;
    const __nv_bfloat16* pAh = Ahg + (size_t)(m0 + row) * K + half * 8;
    const __nv_bfloat16* pAl = Alg + (size_t)(m0 + row) * K + half * 8;
    const __nv_bfloat16* pBh = Bhg + (size_t)(n0 + row) * K + half * 8;
    const __nv_bfloat16* pBl = Blg + (size_t)(n0 + row) * K + half * 8;
    const uint32_t sdb = (uint32_t)((row * RP + half * 8) * 2);   // byte offset

    uint32_t a_off[4], b_off[4];
    {
        const int ar = lane & 15, ak = (lane >> 4) * 16;
        const int bn = lane & 7,  bk = ((lane >> 3) & 1) * 16;
#pragma unroll
        for (int i = 0; i < 4; i++) a_off[i] = (uint32_t)((wm*64 + i*16 + ar) * (RP*2) + ak);
#pragma unroll
        for (int j = 0; j < 4; j++) b_off[j] = (uint32_t)((wn*32 + j*8 + bn) * (RP*2) + bk);
    }

    float acc[4][4][4];
#pragma unroll
    for (int i = 0; i < 4; i++)
#pragma unroll
        for (int j = 0; j < 4; j++)
#pragma unroll
            for (int t = 0; t < 4; t++) acc[i][j][t] = 0.0f;

    const int NC = K >> 4;   // 48

    // prologue: chunks 0,1 -> bufs 0,1 (two commit groups)
#pragma unroll
    for (int p = 0; p < 2; p++) {
        const uint32_t d = (uint32_t)p * GBUF + sdb;
        cp_async16(bAh + d, pAh + p*16);
        cp_async16(bAl + d, pAl + p*16);
        cp_async16(bBh + d, pBh + p*16);
        cp_async16(bBl + d, pBl + p*16);
        cp_commit();
    }

    for (int kc = 0; kc < NC; kc++) {
        const uint32_t bo = (uint32_t)(kc % 3) * GBUF;
        if (kc + 1 < NC) cp_wait1(); else cp_wait0();
        __syncthreads();                    // chunk kc visible; buf reuse safe
        if (kc + 2 < NC) {
            const int ko = (kc + 2) * 16;
            const uint32_t dq = (uint32_t)((kc + 2) % 3) * GBUF + sdb;
            cp_async16(bAh + dq, pAh + ko);
            cp_async16(bAl + dq, pAl + ko);
            cp_async16(bBh + dq, pBh + ko);
            cp_async16(bBl + dq, pBl + ko);
            cp_commit();
        }

        uint32_t fbh[4][2], fbl[4][2];
#pragma unroll
        for (int j = 0; j < 4; j++) {
            ldm_x2(fbh[j], bBh + bo + b_off[j]);
            ldm_x2(fbl[j], bBl + bo + b_off[j]);
        }
        uint32_t fah[2][4], fal[2][4];
        ldm_x4(fah[0], bAh + bo + a_off[0]);
        ldm_x4(fal[0], bAl + bo + a_off[0]);
#pragma unroll
        for (int i = 0; i < 4; i++) {
            const int cur = i & 1;
            if (i < 3) {
                ldm_x4(fah[cur ^ 1], bAh + bo + a_off[i + 1]);
                ldm_x4(fal[cur ^ 1], bAl + bo + a_off[i + 1]);
            }
#pragma unroll
            for (int j = 0; j < 4; j++) mma_bf16(acc[i][j], fah[cur], fbh[j]);
#pragma unroll
            for (int j = 0; j < 4; j++) mma_bf16(acc[i][j], fah[cur], fbl[j]);
#pragma unroll
            for (int j = 0; j < 4; j++) mma_bf16(acc[i][j], fal[cur], fbh[j]);
        }
    }

    const int lr = lane >> 2;
    const int lc = (lane & 3) << 1;
#pragma unroll
    for (int i = 0; i < 4; i++) {
        const int m = m0 + wm*64 + i*16 + lr;
#pragma unroll
        for (int j = 0; j < 4; j++) {
            const int n = n0 + wn*32 + j*8 + lc;
            const float b0 = bias[n], b1 = bias[n + 1];
            const float v00 = acc[i][j][0] + b0, v01 = acc[i][j][1] + b1;
            const float v10 = acc[i][j][2] + b0, v11 = acc[i][j][3] + b1;
            if (MODE == 0) {
                *(float2*)(C + (size_t)m * N + n) = make_float2(v00, v01);
                *(float2*)(C + (size_t)(m + 8) * N + n) = make_float2(v10, v11);
            } else {
                const int sect = n0 / NX;            // 0=Q,1=K,2=V
                const int nn = n - sect * NX;
                const int d  = nn & 63;
                const int b  = m >> 11;
                const int sq = m & (SEQ - 1);
                __nv_bfloat16* Hd = (sect == 0) ? g_Qh : (sect == 1) ? g_Kh : g_Vh;
                __nv_bfloat16* Ld = (sect == 0) ? g_Ql : (sect == 1) ? g_Kl : g_Vl;
                // Quirky direct reshape: t = sq*NH + nn/64 -> (h, s2)
                const int t0 = sq * NH + (nn >> 6);
                const int h0 = t0 >> 11, s20 = t0 & (SEQ - 1);
                const int t1 = (sq + 8) * NH + (nn >> 6);     // row m+8, same b
                const int h1 = t1 >> 11, s21 = t1 & (SEQ - 1);
                const size_t base0 = ((size_t)(b*NH + h0) * SEQ + s20) * HD + d;
                const size_t base1 = ((size_t)(b*NH + h1) * SEQ + s21) * HD + d;
                uint32_t hi0, lo0, hi1, lo1;
                split2(v00, v01, hi0, lo0);
                split2(v10, v11, hi1, lo1);
                *(uint32_t*)(Hd + base0) = hi0;
                *(uint32_t*)(Ld + base0) = lo0;
                *(uint32_t*)(Hd + base1) = hi1;
                *(uint32_t*)(Ld + base1) = lo1;
            }
        }
    }
}

// ---------------------------------------------------------------------------
// HMMA flash attention: q-tile 128, k-tile 64, 8 warps x 16 q-rows.
// Q hi/lo in SMEM, K/V cp.async double-buffered, 2 CTAs/SM.
// R14: fragment loads software-pipelined one step ahead in both S and P@V
// phases; fully-masked per-warp tiles skipped (mathematical no-op).
// ---------------------------------------------------------------------------
#define ARP 72
#define ARPB (ARP*2)
#define QTILEB (128*ARPB)           // 18432 B per Q array
#define ATILE (64*ARPB)             // 9216 B per K/V array per buffer
#define ASTRIDE (2*ATILE)
#define ATTN_SMEM (2*QTILEB + 4*ASTRIDE)   // 110592 B

__global__ void __launch_bounds__(256, 2)
attn_mma(const float* __restrict__ amask)
{
    extern __shared__ __nv_bfloat16 dynsm[];

    const int tid  = threadIdx.x;
    const int wid  = tid >> 5;
    const int lane = tid & 31;
    const int qb = gridDim.x - 1 - blockIdx.x;   // long CTAs first
    const int h  = blockIdx.y;
    const int b  = blockIdx.z;
    const int q0 = qb * 128;
    const int qw = q0 + wid * 16;                // warp's 16 q-rows

    const size_t hoff = (size_t)(b*NH + h) * SEQ * HD;
    const __nv_bfloat16* Qg = g_Qh + hoff;
    const __nv_bfloat16* Qlg = g_Ql + hoff;
    const __nv_bfloat16* Kh = g_Kh + hoff;
    const __nv_bfloat16* Kl = g_Kl + hoff;
    const __nv_bfloat16* Vh = g_Vh + hoff;
    const __nv_bfloat16* Vl = g_Vl + hoff;
    const float* am = amask + (size_t)b * SEQ;

    const int r  = lane >> 2;          // 0..7
    const int c2 = (lane & 3) << 1;    // 0,2,4,6

    const uint32_t sm0 = smem_u32(dynsm);
    const uint32_t bQh = sm0;
    const uint32_t bQl = sm0 + QTILEB;
    const uint32_t kvb = sm0 + 2*QTILEB;
    const uint32_t bKh = kvb;
    const uint32_t bKl = kvb + ASTRIDE;
    const uint32_t bVh = kvb + 2*ASTRIDE;
    const uint32_t bVl = kvb + 3*ASTRIDE;

    // lane addresses
    const uint32_t qa_off = (uint32_t)((wid*16 + (lane & 15)) * ARPB + (lane >> 4) * 16);
    uint32_t kb4_off[4];
#pragma unroll
    for (int jp = 0; jp < 4; jp++)
        kb4_off[jp] = (uint32_t)((jp*16 + (lane >> 4)*8 + (lane & 7)) * ARPB
                                 + ((lane >> 3) & 1) * 16);
    const uint32_t vt4 = (uint32_t)((lane & 15) * ARPB + (lane >> 4) * 16);

    float acc[8][4];
#pragma unroll
    for (int j = 0; j < 8; j++)
#pragma unroll
        for (int t = 0; t < 4; t++) acc[j][t] = 0.0f;
    float mrow0 = -3.0e38f, mrow1 = -3.0e38f, lrow0 = 0.0f, lrow1 = 0.0f;

    // K/V tile loaders: full 64x64, 2 x 16B per thread per array
    const int trow = tid >> 3;
    const int tcol = (tid & 7) << 3;
    const uint32_t tdst = (uint32_t)(trow * ARPB + tcol * 2);

    const int nkb = 2 * qb + 2;
    const int qr0 = qw + r, qr1 = qw + r + 8;

    // prologue: Q tile (once) + K/V tile 0 -> buf 0
    {
        const int qrow = tid >> 1;
        const int qcb  = (tid & 1) * 32;           // elems
        const uint32_t qd = (uint32_t)(qrow * ARPB + qcb * 2);
        const size_t qs = (size_t)(q0 + qrow) * HD + qcb;
#pragma unroll
        for (int c = 0; c < 4; c++) {
            cp_async16(bQh + qd + c*16, Qg  + qs + c*8);
            cp_async16(bQl + qd + c*16, Qlg + qs + c*8);
        }
#pragma unroll
        for (int it = 0; it < 2; it++) {
            const int rr = trow + it * 32;
            const size_t src = (size_t)rr * HD + tcol;
            const uint32_t dst = tdst + (uint32_t)(it * 32 * ARPB);
            cp_async16(bKh + dst, Kh + src);
            cp_async16(bKl + dst, Kl + src);
            cp_async16(bVh + dst, Vh + src);
            cp_async16(bVl + dst, Vl + src);
        }
        cp_commit();
    }

    for (int kb = 0; kb < nkb; kb++) {
        const int k0 = kb * 64;
        const uint32_t bo = (uint32_t)(kb & 1) * ATILE;
        cp_wait0();
        __syncthreads();                 // tile kb (and Q on kb=0) visible
        if (kb + 1 < nkb) {
            const int kn = k0 + 64;
            const uint32_t bq = (uint32_t)((kb + 1) & 1) * ATILE;
#pragma unroll
            for (int it = 0; it < 2; it++) {
                const int rr = trow + it * 32;
                const size_t src = (size_t)(kn + rr) * HD + tcol;
                const uint32_t dst = bq + tdst + (uint32_t)(it * 32 * ARPB);
                cp_async16(bKh + dst, Kh + src);
                cp_async16(bKl + dst, Kl + src);
                cp_async16(bVh + dst, Vh + src);
                cp_async16(bVl + dst, Vl + src);
            }
            cp_commit();
        }

        // skip per-warp fully-masked tile (no-op: masked lanes underflow,
        // corr=1, rsum=0).  Warp-uniform condition.
        if (qw + 15 < k0) continue;

        // S = Q @ K^T (3-product), fragment loads pipelined one step ahead
        float s[8][4];
#pragma unroll
        for (int j = 0; j < 8; j++)
#pragma unroll
            for (int t = 0; t < 4; t++) s[j][t] = 0.0f;
        {
            uint32_t fqh[2][4], fql[2][4], fkh[2][4], fkl[2][4];
            ldm_x4(fqh[0], bQh + qa_off);
            ldm_x4(fql[0], bQl + qa_off);
            ldm_x4(fkh[0], bKh + bo + kb4_off[0]);
            ldm_x4(fkl[0], bKl + bo + kb4_off[0]);
#pragma unroll
            for (int idx = 0; idx < 16; idx++) {
                const int ds = idx >> 2, jp = idx & 3;
                const int kc = idx & 1, qc = ds & 1;
                if (idx < 15) {
                    const int nds = (idx + 1) >> 2, njp = (idx + 1) & 3;
                    ldm_x4(fkh[kc ^ 1], bKh + bo + kb4_off[njp] + nds * 32);
                    ldm_x4(fkl[kc ^ 1], bKl + bo + kb4_off[njp] + nds * 32);
                    if (njp == 0) {
                        ldm_x4(fqh[qc ^ 1], bQh + qa_off + nds * 32);
                        ldm_x4(fql[qc ^ 1], bQl + qa_off + nds * 32);
                    }
                }
                mma_bf16(s[2*jp],   fqh[qc], fkh[kc] + 0);
                mma_bf16(s[2*jp+1], fqh[qc], fkh[kc] + 2);
                mma_bf16(s[2*jp],   fqh[qc], fkl[kc] + 0);
                mma_bf16(s[2*jp+1], fqh[qc], fkl[kc] + 2);
                mma_bf16(s[2*jp],   fql[qc], fkh[kc] + 0);
                mma_bf16(s[2*jp+1], fql[qc], fkh[kc] + 2);
            }
        }

        // mask + online softmax (rows qr0, qr1)
        float rmax0 = -3.0e38f, rmax1 = -3.0e38f;
#pragma unroll
        for (int j = 0; j < 8; j++) {
            const int k = k0 + j*8 + c2;
            const float2 amv = *(const float2*)(am + k);
            s[j][0] = (k   <= qr0) ? s[j][0]*0.125f + amv.x : -10000.0f + amv.x;
            s[j][1] = (k+1 <= qr0) ? s[j][1]*0.125f + amv.y : -10000.0f + amv.y;
            s[j][2] = (k   <= qr1) ? s[j][2]*0.125f + amv.x : -10000.0f + amv.x;
            s[j][3] = (k+1 <= qr1) ? s[j][3]*0.125f + amv.y : -10000.0f + amv.y;
            rmax0 = fmaxf(rmax0, fmaxf(s[j][0], s[j][1]));
            rmax1 = fmaxf(rmax1, fmaxf(s[j][2], s[j][3]));
        }
        rmax0 = fmaxf(rmax0, __shfl_xor_sync(0xffffffffu, rmax0, 1));
        rmax0 = fmaxf(rmax0, __shfl_xor_sync(0xffffffffu, rmax0, 2));
        rmax1 = fmaxf(rmax1, __shfl_xor_sync(0xffffffffu, rmax1, 1));
        rmax1 = fmaxf(rmax1, __shfl_xor_sync(0xffffffffu, rmax1, 2));
        const float mnew0 = fmaxf(mrow0, rmax0);
        const float mnew1 = fmaxf(mrow1, rmax1);
        const float corr0 = __expf(mrow0 - mnew0);
        const float corr1 = __expf(mrow1 - mnew1);
        float rsum0 = 0.0f, rsum1 = 0.0f;
#pragma unroll
        for (int j = 0; j < 8; j++) {
            s[j][0] = __expf(s[j][0] - mnew0);
            s[j][1] = __expf(s[j][1] - mnew0);
            s[j][2] = __expf(s[j][2] - mnew1);
            s[j][3] = __expf(s[j][3] - mnew1);
            rsum0 += s[j][0] + s[j][1];
            rsum1 += s[j][2] + s[j][3];
        }
        rsum0 += __shfl_xor_sync(0xffffffffu, rsum0, 1);
        rsum0 += __shfl_xor_sync(0xffffffffu, rsum0, 2);
        rsum1 += __shfl_xor_sync(0xffffffffu, rsum1, 1);
        rsum1 += __shfl_xor_sync(0xffffffffu, rsum1, 2);
        lrow0 = lrow0 * corr0 + rsum0;
        lrow1 = lrow1 * corr1 + rsum1;
        mrow0 = mnew0; mrow1 = mnew1;
#pragma unroll
        for (int j = 0; j < 8; j++) {
            acc[j][0] *= corr0; acc[j][1] *= corr0;
            acc[j][2] *= corr1; acc[j][3] *= corr1;
        }

        // P fragments (register repack: A-frag t from S n-frags 2t, 2t+1)
        uint32_t fph[4][4], fpl[4][4];
#pragma unroll
        for (int t = 0; t < 4; t++) {
            split2(s[2*t][0],   s[2*t][1],   fph[t][0], fpl[t][0]);
            split2(s[2*t][2],   s[2*t][3],   fph[t][1], fpl[t][1]);
            split2(s[2*t+1][0], s[2*t+1][1], fph[t][2], fpl[t][2]);
            split2(s[2*t+1][2], s[2*t+1][3], fph[t][3], fpl[t][3]);
        }

        // O += P @ V (3-product; V x4.trans), loads pipelined one step ahead
        {
            uint32_t fvh[2][4], fvl[2][4];
            ldm_x4t(fvh[0], bVh + bo + vt4);
            ldm_x4t(fvl[0], bVl + bo + vt4);
#pragma unroll
            for (int idx = 0; idx < 16; idx++) {
                const int t = idx >> 2, dnp = idx & 3;
                const int vc = idx & 1;
                if (idx < 15) {
                    const int nt = (idx + 1) >> 2, ndnp = (idx + 1) & 3;
                    const uint32_t na = bo + vt4 + (uint32_t)(nt * 16 * ARPB) + ndnp * 32;
                    ldm_x4t(fvh[vc ^ 1], bVh + na);
                    ldm_x4t(fvl[vc ^ 1], bVl + na);
                }
                mma_bf16(acc[2*dnp],   fph[t], fvh[vc] + 0);
                mma_bf16(acc[2*dnp+1], fph[t], fvh[vc] + 2);
                mma_bf16(acc[2*dnp],   fph[t], fvl[vc] + 0);
                mma_bf16(acc[2*dnp+1], fph[t], fvl[vc] + 2);
                mma_bf16(acc[2*dnp],   fpl[t], fvh[vc] + 0);
                mma_bf16(acc[2*dnp+1], fpl[t], fvh[vc] + 2);
            }
        }
    }

    // epilogue: normalize, bf16 hi/lo split into g_Ah/g_Al at [b, q_view, h*64+d]
    const float inv0 = 1.0f / lrow0;
    const float inv1 = 1.0f / lrow1;
#pragma unroll
    for (int dn = 0; dn < 8; dn++) {
        const int d = dn*8 + c2;
        uint32_t hi0, lo0, hi1, lo1;
        split2(acc[dn][0]*inv0, acc[dn][1]*inv0, hi0, lo0);
        split2(acc[dn][2]*inv1, acc[dn][3]*inv1, hi1, lo1);
        const size_t i0 = ((size_t)b * SEQ + qr0) * NX + h * HD + d;
        const size_t i1 = ((size_t)b * SEQ + qr1) * NX + h * HD + d;
        *(uint32_t*)(g_Ah + i0) = hi0;
        *(uint32_t*)(g_Al + i0) = lo0;
        *(uint32_t*)(g_Ah + i1) = hi1;
        *(uint32_t*)(g_Al + i1) = lo1;
    }
}

// ---------------------------------------------------------------------------
extern "C" void kernel_launch(void* const* d_in, const int* in_sizes, int n_in,
                              void* d_out, int out_size)
{
    const float* hidden = (const float*)d_in[0];
    const float* amask  = (const float*)d_in[1];
    const float* w_attn = (const float*)d_in[2];
    const float* b_attn = (const float*)d_in[3];
    const float* w_proj = (const float*)d_in[4];
    const float* b_proj = (const float*)d_in[5];
    float* out = (float*)d_out;

    // Host-side attribute sets: not stream ops, graph-capture-safe, idempotent.
    cudaFuncSetAttribute(attn_mma, cudaFuncAttributeMaxDynamicSharedMemorySize,
                         ATTN_SMEM);
    cudaFuncSetAttribute(mma_gemm_impl, cudaFuncAttributeMaxDynamicSharedMemorySize,
                         GEMM_SMEM);

    __nv_bfloat16 *Bh1, *Bl1, *Bh2, *Bl2, *Ah, *Al;
    cudaGetSymbolAddress((void**)&Bh1, g_Bh1);
    cudaGetSymbolAddress((void**)&Bl1, g_Bl1);
    cudaGetSymbolAddress((void**)&Bh2, g_Bh2);
    cudaGetSymbolAddress((void**)&Bl2, g_Bl2);
    cudaGetSymbolAddress((void**)&Ah,  g_Ah);
    cudaGetSymbolAddress((void**)&Al,  g_Al);

    // Pre-pass: transpose+split weights, split activations
    wsplitT<<<dim3(NQKV/32, NX/32), 256>>>(w_attn, Bh1, Bl1, NX, NQKV);
    wsplitT<<<dim3(NX/32,   NX/32), 256>>>(w_proj, Bh2, Bl2, NX, NX);
    asplit<<<(MROWS*NX)/(256*4), 256>>>(hidden, Ah, Al);

    // 1) QKV = X @ W_attn + b -> bf16 hi/lo Q/K/V, quirky per-head layout
    mma_gemm_impl<<<dim3(NQKV/128, MROWS/128), 256, GEMM_SMEM>>>(
        Ah, Al, Bh1, Bl1, b_attn, nullptr, NQKV, NX, 1);

    // 2) HMMA flash attention -> bf16 hi/lo activations
    attn_mma<<<dim3(SEQ/128, NH, BSZ), 256, ATTN_SMEM>>>(amask);

    // 3) out = A @ W_proj + b
    mma_gemm_impl<<<dim3(NX/128, MROWS/128), 256, GEMM_SMEM>>>(
        Ah, Al, Bh2, Bl2, b_proj, out, NX, NX, 0);
}

// round 15
// speedup vs baseline: 1.1063x; 1.1063x over previous
#include <cuda_runtime.h>
#include <cuda_fp16.h>
#include <math.h>
#include <stdint.h>

#define BSZ 2
#define SEQ 2048
#define NX 768
#define NH 12
#define HD 64
#define MROWS (BSZ*SEQ)      // 4096
#define NQKV (3*NX)          // 2304

// Scratch (no cudaMalloc allowed) — all fp16 now
__device__ __half g_Qh[BSZ*NH*SEQ*HD];
__device__ __half g_Ql[BSZ*NH*SEQ*HD];
__device__ __half g_Kh[BSZ*NH*SEQ*HD];
__device__ __half g_Kl[BSZ*NH*SEQ*HD];
__device__ __half g_Vh[BSZ*NH*SEQ*HD];
__device__ __half g_Vl[BSZ*NH*SEQ*HD];
__device__ __half g_Ah[BSZ*SEQ*NX];   // attn out hi (feeds proj)
__device__ __half g_Al[BSZ*SEQ*NX];   // attn out lo
__device__ __half g_Bh1[NQKV*NX];     // w_attn^T hi  [2304][768]
__device__ __half g_Bl1[NQKV*NX];
__device__ __half g_Bh2[NX*NX];       // w_proj^T hi  [768][768]
__device__ __half g_Bl2[NX*NX];

// ---------------------------------------------------------------------------
// helpers
// ---------------------------------------------------------------------------
__device__ __forceinline__ uint32_t smem_u32(const void* p) {
    uint32_t a;
    asm("{ .reg .u64 t; cvta.to.shared.u64 t, %1; cvt.u32.u64 %0, t; }"
        : "=r"(a) : "l"(p));
    return a;
}
__device__ __forceinline__ void mma_f16(float* d, const uint32_t* a, const uint32_t* b) {
    asm volatile(
        "mma.sync.aligned.m16n8k16.row.col.f32.f16.f16.f32 "
        "{%0,%1,%2,%3}, {%4,%5,%6,%7}, {%8,%9}, {%0,%1,%2,%3};"
        : "+f"(d[0]), "+f"(d[1]), "+f"(d[2]), "+f"(d[3])
        : "r"(a[0]), "r"(a[1]), "r"(a[2]), "r"(a[3]), "r"(b[0]), "r"(b[1]));
}
__device__ __forceinline__ void ldm_x4(uint32_t* r, uint32_t addr) {
    asm volatile("ldmatrix.sync.aligned.m8n8.x4.shared.b16 {%0,%1,%2,%3}, [%4];"
                 : "=r"(r[0]), "=r"(r[1]), "=r"(r[2]), "=r"(r[3]) : "r"(addr));
}
__device__ __forceinline__ void ldm_x4t(uint32_t* r, uint32_t addr) {
    asm volatile("ldmatrix.sync.aligned.m8n8.x4.trans.shared.b16 {%0,%1,%2,%3}, [%4];"
                 : "=r"(r[0]), "=r"(r[1]), "=r"(r[2]), "=r"(r[3]) : "r"(addr));
}
__device__ __forceinline__ void cp_async16(uint32_t dst, const void* src) {
    asm volatile("cp.async.cg.shared.global [%0], [%1], 16;"
                 :: "r"(dst), "l"(src) : "memory");
}
__device__ __forceinline__ void cp_commit() {
    asm volatile("cp.async.commit_group;" ::: "memory");
}
__device__ __forceinline__ void cp_wait0() {
    asm volatile("cp.async.wait_group 0;" ::: "memory");
}
// split two fp32 into packed fp16 hi2 / lo2
__device__ __forceinline__ void split2(float a, float b, uint32_t& hi, uint32_t& lo) {
    __half ha = __float2half_rn(a), hb = __float2half_rn(b);
    __half la = __float2half_rn(a - __half2float(ha));
    __half lb = __float2half_rn(b - __half2float(hb));
    __half2 H = __halves2half2(ha, hb), L = __halves2half2(la, lb);
    hi = *(uint32_t*)&H; lo = *(uint32_t*)&L;
}

// ---------------------------------------------------------------------------
// Pre-pass 1: transpose + fp16-split weights.  B[K,N] fp32 -> Th/Tl [N][K]
// ---------------------------------------------------------------------------
__global__ void __launch_bounds__(256)
wsplitT(const float* __restrict__ B, __half* __restrict__ Th,
        __half* __restrict__ Tl, int K, int N)
{
    __shared__ float t[32][33];
    const int c  = threadIdx.x & 31;
    const int r4 = threadIdx.x >> 5;
    const int n0 = blockIdx.x * 32;
    const int k0 = blockIdx.y * 32;
#pragma unroll
    for (int i = 0; i < 4; i++)
        t[r4 + 8*i][c] = B[(size_t)(k0 + r4 + 8*i) * N + n0 + c];
    __syncthreads();
#pragma unroll
    for (int i = 0; i < 4; i++) {
        const int n = n0 + r4 + 8*i;
        const float v = t[c][r4 + 8*i];
        const __half hi = __float2half_rn(v);
        Th[(size_t)n * K + k0 + c] = hi;
        Tl[(size_t)n * K + k0 + c] = __float2half_rn(v - __half2float(hi));
    }
}

// Pre-pass 2: elementwise fp16 split of activations
__global__ void __launch_bounds__(256)
asplit(const float* __restrict__ X, __half* __restrict__ H,
       __half* __restrict__ L)
{
    const size_t i = (size_t)blockIdx.x * 256 + threadIdx.x;
    float4 x = ((const float4*)X)[i];
    uint32_t h0, l0, h1, l1;
    split2(x.x, x.y, h0, l0);
    split2(x.z, x.w, h1, l1);
    ((uint32_t*)H)[2*i]   = h0;
    ((uint32_t*)H)[2*i+1] = h1;
    ((uint32_t*)L)[2*i]   = l0;
    ((uint32_t*)L)[2*i+1] = l1;
}

// ---------------------------------------------------------------------------
// HMMA fp16 3-product GEMM: C = A @ Bt^T + bias
// R13 2-stage cp.async pipeline (known good), 2 CTAs/SM (reg cap 128).
// R15: Bh/Bl fragments fetched with ONE ldmatrix.x4 (matrices {Bh k0, Bh k1,
// Bl k0, Bl k1} via per-lane-group base selection) — B LDSM halved.
// MODE 1: writes Q/K/V fp16 hi/lo via the reference's QUIRKY direct reshape:
//         flat f = sq*768 + nn -> t = sq*NH + (nn>>6); h = t>>11; s2 = t&2047.
// MODE 0: fp32 C.
// ---------------------------------------------------------------------------
#define RP 24
#define GBUF (128*RP*2)      // bytes per buffer per array
__global__ void __launch_bounds__(256, 2)
mma_gemm_impl(const __half* __restrict__ Ahg, const __half* __restrict__ Alg,
              const __half* __restrict__ Bhg, const __half* __restrict__ Blg,
              const float* __restrict__ bias, float* __restrict__ C,
              int N, int K, int MODE)
{
    __shared__ __half sAh[2][128*RP];
    __shared__ __half sAl[2][128*RP];
    __shared__ __half sBh[2][128*RP];
    __shared__ __half sBl[2][128*RP];

    const int tid  = threadIdx.x;
    const int wid  = tid >> 5;
    const int lane = tid & 31;
    const int wm   = wid >> 2;
    const int wn   = wid & 3;
    const int m0 = blockIdx.y * 128;
    const int n0 = blockIdx.x * 128;

    const int row  = tid >> 1;
    const int half = tid & 1;
    const __half* pAh = Ahg + (size_t)(m0 + row) * K + half * 8;
    const __half* pAl = Alg + (size_t)(m0 + row) * K + half * 8;
    const __half* pBh = Bhg + (size_t)(n0 + row) * K + half * 8;
    const __half* pBl = Blg + (size_t)(n0 + row) * K + half * 8;
    const uint32_t sdb = (uint32_t)((row * RP + half * 8) * 2);   // byte offset

    const uint32_t bAh = smem_u32(sAh), bAl = smem_u32(sAl);
    const uint32_t bBh = smem_u32(sBh), bBl = smem_u32(sBl);
    uint32_t a_off[4];
    uint32_t b_addr[4];   // absolute smem addr (selects sBh or sBl by lane group)
    {
        const int ar = lane & 15, ak = (lane >> 4) * 16;
#pragma unroll
        for (int i = 0; i < 4; i++) a_off[i] = (uint32_t)((wm*64 + i*16 + ar) * (RP*2) + ak);
        // merged B x4: group g = lane>>3; matrices {Bh k0, Bh k1, Bl k0, Bl k1}
        const int g  = lane >> 3;
        const int bn = lane & 7;
        const uint32_t base = (g < 2) ? bBh : bBl;
        const uint32_t bk = (uint32_t)((g & 1) * 16);
#pragma unroll
        for (int j = 0; j < 4; j++)
            b_addr[j] = base + (uint32_t)((wn*32 + j*8 + bn) * (RP*2)) + bk;
    }

    float acc[4][4][4];
#pragma unroll
    for (int i = 0; i < 4; i++)
#pragma unroll
        for (int j = 0; j < 4; j++)
#pragma unroll
            for (int t = 0; t < 4; t++) acc[i][j][t] = 0.0f;

    const int NC = K >> 4;

    // prologue: chunk 0 -> buf 0
    {
        cp_async16(bAh + sdb, pAh);
        cp_async16(bAl + sdb, pAl);
        cp_async16(bBh + sdb, pBh);
        cp_async16(bBl + sdb, pBl);
        cp_commit();
    }

    for (int kc = 0; kc < NC; kc++) {
        const int buf = kc & 1;
        const uint32_t bo = (uint32_t)buf * GBUF;
        cp_wait0();
        __syncthreads();                    // chunk kc visible; buf^1 reads done
        if (kc + 1 < NC) {
            const int ko = (kc + 1) * 16;
            const uint32_t dq = (uint32_t)(buf ^ 1) * GBUF + sdb;
            cp_async16(bAh + dq, pAh + ko);
            cp_async16(bAl + dq, pAl + ko);
            cp_async16(bBh + dq, pBh + ko);
            cp_async16(bBl + dq, pBl + ko);
            cp_commit();
        }

        // merged B fragments: fb[j] = {bh0, bh1, bl0, bl1}
        uint32_t fb[4][4];
#pragma unroll
        for (int j = 0; j < 4; j++) ldm_x4(fb[j], b_addr[j] + bo);
#pragma unroll
        for (int i = 0; i < 4; i++) {
            uint32_t fah[4], fal[4];
            ldm_x4(fah, bAh + bo + a_off[i]);
            ldm_x4(fal, bAl + bo + a_off[i]);
#pragma unroll
            for (int j = 0; j < 4; j++) mma_f16(acc[i][j], fah, fb[j] + 0);
#pragma unroll
            for (int j = 0; j < 4; j++) mma_f16(acc[i][j], fah, fb[j] + 2);
#pragma unroll
            for (int j = 0; j < 4; j++) mma_f16(acc[i][j], fal, fb[j] + 0);
        }
    }

    const int lr = lane >> 2;
    const int lc = (lane & 3) << 1;
#pragma unroll
    for (int i = 0; i < 4; i++) {
        const int m = m0 + wm*64 + i*16 + lr;
#pragma unroll
        for (int j = 0; j < 4; j++) {
            const int n = n0 + wn*32 + j*8 + lc;
            const float b0 = bias[n], b1 = bias[n + 1];
            const float v00 = acc[i][j][0] + b0, v01 = acc[i][j][1] + b1;
            const float v10 = acc[i][j][2] + b0, v11 = acc[i][j][3] + b1;
            if (MODE == 0) {
                *(float2*)(C + (size_t)m * N + n) = make_float2(v00, v01);
                *(float2*)(C + (size_t)(m + 8) * N + n) = make_float2(v10, v11);
            } else {
                const int sect = n0 / NX;            // 0=Q,1=K,2=V
                const int nn = n - sect * NX;
                const int d  = nn & 63;
                const int b  = m >> 11;
                const int sq = m & (SEQ - 1);
                __half* Hd = (sect == 0) ? g_Qh : (sect == 1) ? g_Kh : g_Vh;
                __half* Ld = (sect == 0) ? g_Ql : (sect == 1) ? g_Kl : g_Vl;
                // Quirky direct reshape: t = sq*NH + nn/64 -> (h, s2)
                const int t0 = sq * NH + (nn >> 6);
                const int h0 = t0 >> 11, s20 = t0 & (SEQ - 1);
                const int t1 = (sq + 8) * NH + (nn >> 6);     // row m+8, same b
                const int h1 = t1 >> 11, s21 = t1 & (SEQ - 1);
                const size_t base0 = ((size_t)(b*NH + h0) * SEQ + s20) * HD + d;
                const size_t base1 = ((size_t)(b*NH + h1) * SEQ + s21) * HD + d;
                uint32_t hi0, lo0, hi1, lo1;
                split2(v00, v01, hi0, lo0);
                split2(v10, v11, hi1, lo1);
                *(uint32_t*)(Hd + base0) = hi0;
                *(uint32_t*)(Ld + base0) = lo0;
                *(uint32_t*)(Hd + base1) = hi1;
                *(uint32_t*)(Ld + base1) = lo1;
            }
        }
    }
}

// ---------------------------------------------------------------------------
// HMMA flash attention: q-tile 128, k-tile 64, 8 warps x 16 q-rows.
// Q hi/lo in SMEM, K/V cp.async double-buffered, 2 CTAs/SM.
// R15: fp16; S-phase 2-product  S = (Qh+Ql)*Kh  (Kl term dropped: |Kl| <=
// 2^-12|K| -> eps_S ~8e-5 after the 0.125 scale).  P@V stays 3-product.
// Fully-masked per-warp tiles skipped (mathematical no-op).
// ---------------------------------------------------------------------------
#define ARP 72
#define ARPB (ARP*2)
#define QTILEB (128*ARPB)           // 18432 B per Q array
#define ATILE (64*ARPB)             // 9216 B per K/V array per buffer
#define ASTRIDE (2*ATILE)
#define ATTN_SMEM (2*QTILEB + 4*ASTRIDE)   // 110592 B (Kl buffer unused but kept
                                           // for layout symmetry of loader)

__global__ void __launch_bounds__(256, 2)
attn_mma(const float* __restrict__ amask)
{
    extern __shared__ __half dynsm[];

    const int tid  = threadIdx.x;
    const int wid  = tid >> 5;
    const int lane = tid & 31;
    const int qb = gridDim.x - 1 - blockIdx.x;   // long CTAs first
    const int h  = blockIdx.y;
    const int b  = blockIdx.z;
    const int q0 = qb * 128;
    const int qw = q0 + wid * 16;                // warp's 16 q-rows

    const size_t hoff = (size_t)(b*NH + h) * SEQ * HD;
    const __half* Qg  = g_Qh + hoff;
    const __half* Qlg = g_Ql + hoff;
    const __half* Kh  = g_Kh + hoff;
    const __half* Vh  = g_Vh + hoff;
    const __half* Vl  = g_Vl + hoff;
    const float* am = amask + (size_t)b * SEQ;

    const int r  = lane >> 2;          // 0..7
    const int c2 = (lane & 3) << 1;    // 0,2,4,6

    const uint32_t sm0 = smem_u32(dynsm);
    const uint32_t bQh = sm0;
    const uint32_t bQl = sm0 + QTILEB;
    const uint32_t kvb = sm0 + 2*QTILEB;
    const uint32_t bKh = kvb;
    const uint32_t bVh = kvb + ASTRIDE;
    const uint32_t bVl = kvb + 2*ASTRIDE;

    // lane addresses
    const uint32_t qa_off = (uint32_t)((wid*16 + (lane & 15)) * ARPB + (lane >> 4) * 16);
    uint32_t kb4_off[4];
#pragma unroll
    for (int jp = 0; jp < 4; jp++)
        kb4_off[jp] = (uint32_t)((jp*16 + (lane >> 4)*8 + (lane & 7)) * ARPB
                                 + ((lane >> 3) & 1) * 16);
    const uint32_t vt4 = (uint32_t)((lane & 15) * ARPB + (lane >> 4) * 16);

    float acc[8][4];
#pragma unroll
    for (int j = 0; j < 8; j++)
#pragma unroll
        for (int t = 0; t < 4; t++) acc[j][t] = 0.0f;
    float mrow0 = -3.0e38f, mrow1 = -3.0e38f, lrow0 = 0.0f, lrow1 = 0.0f;

    // K/V tile loaders: full 64x64, 2 x 16B per thread per array
    const int trow = tid >> 3;
    const int tcol = (tid & 7) << 3;
    const uint32_t tdst = (uint32_t)(trow * ARPB + tcol * 2);

    const int nkb = 2 * qb + 2;
    const int qr0 = qw + r, qr1 = qw + r + 8;

    // prologue: Q tile (once) + K/V tile 0 -> buf 0
    {
        const int qrow = tid >> 1;
        const int qcb  = (tid & 1) * 32;           // elems
        const uint32_t qd = (uint32_t)(qrow * ARPB + qcb * 2);
        const size_t qs = (size_t)(q0 + qrow) * HD + qcb;
#pragma unroll
        for (int c = 0; c < 4; c++) {
            cp_async16(bQh + qd + c*16, Qg  + qs + c*8);
            cp_async16(bQl + qd + c*16, Qlg + qs + c*8);
        }
#pragma unroll
        for (int it = 0; it < 2; it++) {
            const int rr = trow + it * 32;
            const size_t src = (size_t)rr * HD + tcol;
            const uint32_t dst = tdst + (uint32_t)(it * 32 * ARPB);
            cp_async16(bKh + dst, Kh + src);
            cp_async16(bVh + dst, Vh + src);
            cp_async16(bVl + dst, Vl + src);
        }
        cp_commit();
    }

    for (int kb = 0; kb < nkb; kb++) {
        const int k0 = kb * 64;
        const uint32_t bo = (uint32_t)(kb & 1) * ATILE;
        cp_wait0();
        __syncthreads();                 // tile kb (and Q on kb=0) visible
        if (kb + 1 < nkb) {
            const int kn = k0 + 64;
            const uint32_t bq = (uint32_t)((kb + 1) & 1) * ATILE;
#pragma unroll
            for (int it = 0; it < 2; it++) {
                const int rr = trow + it * 32;
                const size_t src = (size_t)(kn + rr) * HD + tcol;
                const uint32_t dst = bq + tdst + (uint32_t)(it * 32 * ARPB);
                cp_async16(bKh + dst, Kh + src);
                cp_async16(bVh + dst, Vh + src);
                cp_async16(bVl + dst, Vl + src);
            }
            cp_commit();
        }

        // skip per-warp fully-masked tile (no-op: masked lanes underflow,
        // corr=1, rsum=0).  Warp-uniform condition.
        if (qw + 15 < k0) continue;

        // S = (Qh+Ql) @ Kh^T  (2-product)
        float s[8][4];
#pragma unroll
        for (int j = 0; j < 8; j++)
#pragma unroll
            for (int t = 0; t < 4; t++) s[j][t] = 0.0f;
#pragma unroll
        for (int ds = 0; ds < 4; ds++) {
            uint32_t fqh[4], fql[4];
            ldm_x4(fqh, bQh + qa_off + ds * 32);
            ldm_x4(fql, bQl + qa_off + ds * 32);
#pragma unroll
            for (int jp = 0; jp < 4; jp++) {
                uint32_t fk[4];
                ldm_x4(fk, bKh + bo + kb4_off[jp] + ds * 32);
                mma_f16(s[2*jp],   fqh, fk + 0);
                mma_f16(s[2*jp+1], fqh, fk + 2);
                mma_f16(s[2*jp],   fql, fk + 0);
                mma_f16(s[2*jp+1], fql, fk + 2);
            }
        }

        // mask + online softmax (rows qr0, qr1)
        float rmax0 = -3.0e38f, rmax1 = -3.0e38f;
#pragma unroll
        for (int j = 0; j < 8; j++) {
            const int k = k0 + j*8 + c2;
            const float2 amv = *(const float2*)(am + k);
            s[j][0] = (k   <= qr0) ? s[j][0]*0.125f + amv.x : -10000.0f + amv.x;
            s[j][1] = (k+1 <= qr0) ? s[j][1]*0.125f + amv.y : -10000.0f + amv.y;
            s[j][2] = (k   <= qr1) ? s[j][2]*0.125f + amv.x : -10000.0f + amv.x;
            s[j][3] = (k+1 <= qr1) ? s[j][3]*0.125f + amv.y : -10000.0f + amv.y;
            rmax0 = fmaxf(rmax0, fmaxf(s[j][0], s[j][1]));
            rmax1 = fmaxf(rmax1, fmaxf(s[j][2], s[j][3]));
        }
        rmax0 = fmaxf(rmax0, __shfl_xor_sync(0xffffffffu, rmax0, 1));
        rmax0 = fmaxf(rmax0, __shfl_xor_sync(0xffffffffu, rmax0, 2));
        rmax1 = fmaxf(rmax1, __shfl_xor_sync(0xffffffffu, rmax1, 1));
        rmax1 = fmaxf(rmax1, __shfl_xor_sync(0xffffffffu, rmax1, 2));
        const float mnew0 = fmaxf(mrow0, rmax0);
        const float mnew1 = fmaxf(mrow1, rmax1);
        const float corr0 = __expf(mrow0 - mnew0);
        const float corr1 = __expf(mrow1 - mnew1);
        float rsum0 = 0.0f, rsum1 = 0.0f;
#pragma unroll
        for (int j = 0; j < 8; j++) {
            s[j][0] = __expf(s[j][0] - mnew0);
            s[j][1] = __expf(s[j][1] - mnew0);
            s[j][2] = __expf(s[j][2] - mnew1);
            s[j][3] = __expf(s[j][3] - mnew1);
            rsum0 += s[j][0] + s[j][1];
            rsum1 += s[j][2] + s[j][3];
        }
        rsum0 += __shfl_xor_sync(0xffffffffu, rsum0, 1);
        rsum0 += __shfl_xor_sync(0xffffffffu, rsum0, 2);
        rsum1 += __shfl_xor_sync(0xffffffffu, rsum1, 1);
        rsum1 += __shfl_xor_sync(0xffffffffu, rsum1, 2);
        lrow0 = lrow0 * corr0 + rsum0;
        lrow1 = lrow1 * corr1 + rsum1;
        mrow0 = mnew0; mrow1 = mnew1;
#pragma unroll
        for (int j = 0; j < 8; j++) {
            acc[j][0] *= corr0; acc[j][1] *= corr0;
            acc[j][2] *= corr1; acc[j][3] *= corr1;
        }

        // P fragments (register repack: A-frag t from S n-frags 2t, 2t+1)
        uint32_t fph[4][4], fpl[4][4];
#pragma unroll
        for (int t = 0; t < 4; t++) {
            split2(s[2*t][0],   s[2*t][1],   fph[t][0], fpl[t][0]);
            split2(s[2*t][2],   s[2*t][3],   fph[t][1], fpl[t][1]);
            split2(s[2*t+1][0], s[2*t+1][1], fph[t][2], fpl[t][2]);
            split2(s[2*t+1][2], s[2*t+1][3], fph[t][3], fpl[t][3]);
        }

        // O += P @ V (3-product; V x4.trans)
#pragma unroll
        for (int t = 0; t < 4; t++) {
            const uint32_t ro = bo + vt4 + (uint32_t)(t * 16 * ARPB);
#pragma unroll
            for (int dnp = 0; dnp < 4; dnp++) {
                uint32_t fvh[4], fvl[4];
                ldm_x4t(fvh, bVh + ro + dnp * 32);
                ldm_x4t(fvl, bVl + ro + dnp * 32);
                mma_f16(acc[2*dnp],   fph[t], fvh + 0);
                mma_f16(acc[2*dnp+1], fph[t], fvh + 2);
                mma_f16(acc[2*dnp],   fph[t], fvl + 0);
                mma_f16(acc[2*dnp+1], fph[t], fvl + 2);
                mma_f16(acc[2*dnp],   fpl[t], fvh + 0);
                mma_f16(acc[2*dnp+1], fpl[t], fvh + 2);
            }
        }
    }

    // epilogue: normalize, fp16 hi/lo split into g_Ah/g_Al at [b, q_view, h*64+d]
    const float inv0 = 1.0f / lrow0;
    const float inv1 = 1.0f / lrow1;
#pragma unroll
    for (int dn = 0; dn < 8; dn++) {
        const int d = dn*8 + c2;
        uint32_t hi0, lo0, hi1, lo1;
        split2(acc[dn][0]*inv0, acc[dn][1]*inv0, hi0, lo0);
        split2(acc[dn][2]*inv1, acc[dn][3]*inv1, hi1, lo1);
        const size_t i0 = ((size_t)b * SEQ + qr0) * NX + h * HD + d;
        const size_t i1 = ((size_t)b * SEQ + qr1) * NX + h * HD + d;
        *(uint32_t*)(g_Ah + i0) = hi0;
        *(uint32_t*)(g_Al + i0) = lo0;
        *(uint32_t*)(g_Ah + i1) = hi1;
        *(uint32_t*)(g_Al + i1) = lo1;
    }
}

// ---------------------------------------------------------------------------
extern "C" void kernel_launch(void* const* d_in, const int* in_sizes, int n_in,
                              void* d_out, int out_size)
{
    const float* hidden = (const float*)d_in[0];
    const float* amask  = (const float*)d_in[1];
    const float* w_attn = (const float*)d_in[2];
    const float* b_attn = (const float*)d_in[3];
    const float* w_proj = (const float*)d_in[4];
    const float* b_proj = (const float*)d_in[5];
    float* out = (float*)d_out;

    // Host-side attribute set: not a stream op, graph-capture-safe, idempotent.
    cudaFuncSetAttribute(attn_mma, cudaFuncAttributeMaxDynamicSharedMemorySize,
                         ATTN_SMEM);

    __half *Bh1, *Bl1, *Bh2, *Bl2, *Ah, *Al;
    cudaGetSymbolAddress((void**)&Bh1, g_Bh1);
    cudaGetSymbolAddress((void**)&Bl1, g_Bl1);
    cudaGetSymbolAddress((void**)&Bh2, g_Bh2);
    cudaGetSymbolAddress((void**)&Bl2, g_Bl2);
    cudaGetSymbolAddress((void**)&Ah,  g_Ah);
    cudaGetSymbolAddress((void**)&Al,  g_Al);

    // Pre-pass: transpose+split weights, split activations
    wsplitT<<<dim3(NQKV/32, NX/32), 256>>>(w_attn, Bh1, Bl1, NX, NQKV);
    wsplitT<<<dim3(NX/32,   NX/32), 256>>>(w_proj, Bh2, Bl2, NX, NX);
    asplit<<<(MROWS*NX)/(256*4), 256>>>(hidden, Ah, Al);

    // 1) QKV = X @ W_attn + b -> fp16 hi/lo Q/K/V, quirky per-head layout
    mma_gemm_impl<<<dim3(NQKV/128, MROWS/128), 256>>>(
        Ah, Al, Bh1, Bl1, b_attn, nullptr, NQKV, NX, 1);

    // 2) HMMA flash attention -> fp16 hi/lo activations
    attn_mma<<<dim3(SEQ/128, NH, BSZ), 256, ATTN_SMEM>>>(amask);

    // 3) out = A @ W_proj + b
    mma_gemm_impl<<<dim3(NX/128, MROWS/128), 256>>>(
        Ah, Al, Bh2, Bl2, b_proj, out, NX, NX, 0);
}

// round 17
// speedup vs baseline: 1.4057x; 1.2706x over previous
#include <cuda_runtime.h>
#include <cuda_fp16.h>
#include <math.h>
#include <stdint.h>

#define BSZ 2
#define SEQ 2048
#define NX 768
#define NH 12
#define HD 64
#define MROWS (BSZ*SEQ)      // 4096
#define NQKV (3*NX)          // 2304

// Scratch (no cudaMalloc allowed)
__device__ __half g_Qh[BSZ*NH*SEQ*HD];
__device__ __half g_Ql[BSZ*NH*SEQ*HD];
__device__ __half g_Kh[BSZ*NH*SEQ*HD];
__device__ __half g_Vh[BSZ*NH*SEQ*HD];
__device__ __half g_Ah[BSZ*SEQ*NX];   // attn out hi (feeds proj)
__device__ __half g_Al[BSZ*SEQ*NX];   // attn out lo
__device__ __half g_Bh1[NQKV*NX];     // w_attn^T hi  [2304][768]
__device__ __half g_Bh2[NX*NX];       // w_proj^T hi  [768][768]

// ---------------------------------------------------------------------------
// helpers
// ---------------------------------------------------------------------------
__device__ __forceinline__ uint32_t smem_u32(const void* p) {
    uint32_t a;
    asm("{ .reg .u64 t; cvta.to.shared.u64 t, %1; cvt.u32.u64 %0, t; }"
        : "=r"(a) : "l"(p));
    return a;
}
__device__ __forceinline__ void mma_f16(float* d, const uint32_t* a, const uint32_t* b) {
    asm volatile(
        "mma.sync.aligned.m16n8k16.row.col.f32.f16.f16.f32 "
        "{%0,%1,%2,%3}, {%4,%5,%6,%7}, {%8,%9}, {%0,%1,%2,%3};"
        : "+f"(d[0]), "+f"(d[1]), "+f"(d[2]), "+f"(d[3])
        : "r"(a[0]), "r"(a[1]), "r"(a[2]), "r"(a[3]), "r"(b[0]), "r"(b[1]));
}
__device__ __forceinline__ void ldm_x4(uint32_t* r, uint32_t addr) {
    asm volatile("ldmatrix.sync.aligned.m8n8.x4.shared.b16 {%0,%1,%2,%3}, [%4];"
                 : "=r"(r[0]), "=r"(r[1]), "=r"(r[2]), "=r"(r[3]) : "r"(addr));
}
__device__ __forceinline__ void ldm_x4t(uint32_t* r, uint32_t addr) {
    asm volatile("ldmatrix.sync.aligned.m8n8.x4.trans.shared.b16 {%0,%1,%2,%3}, [%4];"
                 : "=r"(r[0]), "=r"(r[1]), "=r"(r[2]), "=r"(r[3]) : "r"(addr));
}
__device__ __forceinline__ void cp_async16(uint32_t dst, const void* src) {
    asm volatile("cp.async.cg.shared.global [%0], [%1], 16;"
                 :: "r"(dst), "l"(src) : "memory");
}
__device__ __forceinline__ void cp_commit() {
    asm volatile("cp.async.commit_group;" ::: "memory");
}
__device__ __forceinline__ void cp_wait0() {
    asm volatile("cp.async.wait_group 0;" ::: "memory");
}
// split two fp32 into packed fp16 hi2 / lo2
__device__ __forceinline__ void split2(float a, float b, uint32_t& hi, uint32_t& lo) {
    __half ha = __float2half_rn(a), hb = __float2half_rn(b);
    __half la = __float2half_rn(a - __half2float(ha));
    __half lb = __float2half_rn(b - __half2float(hb));
    __half2 H = __halves2half2(ha, hb), L = __halves2half2(la, lb);
    hi = *(uint32_t*)&H; lo = *(uint32_t*)&L;
}
__device__ __forceinline__ uint32_t pack2h(float a, float b) {
    __half2 H = __halves2half2(__float2half_rn(a), __float2half_rn(b));
    return *(uint32_t*)&H;
}

// ---------------------------------------------------------------------------
// Pre-pass 1: transpose weights to fp16 hi only.  B[K,N] fp32 -> Th [N][K]
// ---------------------------------------------------------------------------
__global__ void __launch_bounds__(256)
wsplitT(const float* __restrict__ B, __half* __restrict__ Th, int K, int N)
{
    __shared__ float t[32][33];
    const int c  = threadIdx.x & 31;
    const int r4 = threadIdx.x >> 5;
    const int n0 = blockIdx.x * 32;
    const int k0 = blockIdx.y * 32;
#pragma unroll
    for (int i = 0; i < 4; i++)
        t[r4 + 8*i][c] = B[(size_t)(k0 + r4 + 8*i) * N + n0 + c];
    __syncthreads();
#pragma unroll
    for (int i = 0; i < 4; i++) {
        const int n = n0 + r4 + 8*i;
        Th[(size_t)n * K + k0 + c] = __float2half_rn(t[c][r4 + 8*i]);
    }
}

// Pre-pass 2: elementwise fp16 split of activations
__global__ void __launch_bounds__(256)
asplit(const float* __restrict__ X, __half* __restrict__ H,
       __half* __restrict__ L)
{
    const size_t i = (size_t)blockIdx.x * 256 + threadIdx.x;
    float4 x = ((const float4*)X)[i];
    uint32_t h0, l0, h1, l1;
    split2(x.x, x.y, h0, l0);
    split2(x.z, x.w, h1, l1);
    ((uint32_t*)H)[2*i]   = h0;
    ((uint32_t*)H)[2*i+1] = h1;
    ((uint32_t*)L)[2*i]   = l0;
    ((uint32_t*)L)[2*i+1] = l1;
}

// ---------------------------------------------------------------------------
// HMMA fp16 2-product GEMM: C = (Ah+Al) @ Bh^T + bias  (weight-lo dropped;
// eps ~ 2^-12/sqrt(3) RMS).  2-stage cp.async, 2 CTAs/SM.
// B-frags: merged ldmatrix.x4 pairs ({j, j+1} x k-halves), like attention K.
// MODE 1: writes Q/K/V fp16 via the reference's QUIRKY direct reshape
//         (lo written only for Q; K/V consumed at fp16 anyway).
// MODE 0: fp32 C.
// ---------------------------------------------------------------------------
#define RP 24
#define RPB (RP*2)
#define GBUF (128*RPB)       // bytes per buffer per array
__global__ void __launch_bounds__(256, 2)
mma_gemm_impl(const __half* __restrict__ Ahg, const __half* __restrict__ Alg,
              const __half* __restrict__ Bhg,
              const float* __restrict__ bias, float* __restrict__ C,
              int N, int K, int MODE)
{
    __shared__ __half sAh[2][128*RP];
    __shared__ __half sAl[2][128*RP];
    __shared__ __half sBh[2][128*RP];

    const int tid  = threadIdx.x;
    const int wid  = tid >> 5;
    const int lane = tid & 31;
    const int wm   = wid >> 2;
    const int wn   = wid & 3;
    const int m0 = blockIdx.y * 128;
    const int n0 = blockIdx.x * 128;

    const int row  = tid >> 1;
    const int half = tid & 1;
    const __half* pAh = Ahg + (size_t)(m0 + row) * K + half * 8;
    const __half* pAl = Alg + (size_t)(m0 + row) * K + half * 8;
    const __half* pBh = Bhg + (size_t)(n0 + row) * K + half * 8;
    const uint32_t sdb = (uint32_t)((row * RP + half * 8) * 2);

    const uint32_t bAh = smem_u32(sAh), bAl = smem_u32(sAl);
    const uint32_t bBh = smem_u32(sBh);
    uint32_t a_off[4], b4_off[2];
    {
        const int ar = lane & 15, ak = (lane >> 4) * 16;
#pragma unroll
        for (int i = 0; i < 4; i++) a_off[i] = (uint32_t)((wm*64 + i*16 + ar) * RPB + ak);
        // merged B x4: matrices {j=2jp k0, j=2jp k1, j=2jp+1 k0, j=2jp+1 k1}
#pragma unroll
        for (int jp = 0; jp < 2; jp++)
            b4_off[jp] = (uint32_t)((wn*32 + jp*16 + (lane >> 4)*8 + (lane & 7)) * RPB
                                    + ((lane >> 3) & 1) * 16);
    }

    float acc[4][4][4];
#pragma unroll
    for (int i = 0; i < 4; i++)
#pragma unroll
        for (int j = 0; j < 4; j++)
#pragma unroll
            for (int t = 0; t < 4; t++) acc[i][j][t] = 0.0f;

    const int NC = K >> 4;

    // prologue: chunk 0 -> buf 0
    {
        cp_async16(bAh + sdb, pAh);
        cp_async16(bAl + sdb, pAl);
        cp_async16(bBh + sdb, pBh);
        cp_commit();
    }

    for (int kc = 0; kc < NC; kc++) {
        const int buf = kc & 1;
        const uint32_t bo = (uint32_t)buf * GBUF;
        cp_wait0();
        __syncthreads();
        if (kc + 1 < NC) {
            const int ko = (kc + 1) * 16;
            const uint32_t dq = (uint32_t)(buf ^ 1) * GBUF + sdb;
            cp_async16(bAh + dq, pAh + ko);
            cp_async16(bAl + dq, pAl + ko);
            cp_async16(bBh + dq, pBh + ko);
            cp_commit();
        }

        uint32_t fb[2][4];
        ldm_x4(fb[0], bBh + bo + b4_off[0]);
        ldm_x4(fb[1], bBh + bo + b4_off[1]);
#pragma unroll
        for (int i = 0; i < 4; i++) {
            uint32_t fah[4], fal[4];
            ldm_x4(fah, bAh + bo + a_off[i]);
            ldm_x4(fal, bAl + bo + a_off[i]);
#pragma unroll
            for (int jp = 0; jp < 2; jp++) {
                mma_f16(acc[i][2*jp],   fah, fb[jp] + 0);
                mma_f16(acc[i][2*jp+1], fah, fb[jp] + 2);
                mma_f16(acc[i][2*jp],   fal, fb[jp] + 0);
                mma_f16(acc[i][2*jp+1], fal, fb[jp] + 2);
            }
        }
    }

    const int lr = lane >> 2;
    const int lc = (lane & 3) << 1;
#pragma unroll
    for (int i = 0; i < 4; i++) {
        const int m = m0 + wm*64 + i*16 + lr;
#pragma unroll
        for (int j = 0; j < 4; j++) {
            const int n = n0 + wn*32 + j*8 + lc;
            const float b0 = bias[n], b1 = bias[n + 1];
            const float v00 = acc[i][j][0] + b0, v01 = acc[i][j][1] + b1;
            const float v10 = acc[i][j][2] + b0, v11 = acc[i][j][3] + b1;
            if (MODE == 0) {
                *(float2*)(C + (size_t)m * N + n) = make_float2(v00, v01);
                *(float2*)(C + (size_t)(m + 8) * N + n) = make_float2(v10, v11);
            } else {
                const int sect = n0 / NX;            // 0=Q,1=K,2=V
                const int nn = n - sect * NX;
                const int d  = nn & 63;
                const int b  = m >> 11;
                const int sq = m & (SEQ - 1);
                // Quirky direct reshape: t = sq*NH + nn/64 -> (h, s2)
                const int t0 = sq * NH + (nn >> 6);
                const int h0 = t0 >> 11, s20 = t0 & (SEQ - 1);
                const int t1 = (sq + 8) * NH + (nn >> 6);     // row m+8, same b
                const int h1 = t1 >> 11, s21 = t1 & (SEQ - 1);
                const size_t base0 = ((size_t)(b*NH + h0) * SEQ + s20) * HD + d;
                const size_t base1 = ((size_t)(b*NH + h1) * SEQ + s21) * HD + d;
                if (sect == 0) {
                    uint32_t hi0, lo0, hi1, lo1;
                    split2(v00, v01, hi0, lo0);
                    split2(v10, v11, hi1, lo1);
                    *(uint32_t*)(g_Qh + base0) = hi0;
                    *(uint32_t*)(g_Ql + base0) = lo0;
                    *(uint32_t*)(g_Qh + base1) = hi1;
                    *(uint32_t*)(g_Ql + base1) = lo1;
                } else {
                    __half* Hd = (sect == 1) ? g_Kh : g_Vh;
                    *(uint32_t*)(Hd + base0) = pack2h(v00, v01);
                    *(uint32_t*)(Hd + base1) = pack2h(v10, v11);
                }
            }
        }
    }
}

// ---------------------------------------------------------------------------
// HMMA flash attention: q-tile 128, k-tile 64, 8 warps x 16 q-rows.
// Q hi/lo in SMEM, K/V cp.async double-buffered, 2 CTAs/SM.
// S = (Qh+Ql)*Kh (2-product);  O += (Ph+Pl)*Vh (2-product).
// Fully-masked per-warp tiles skipped (mathematical no-op).
// ---------------------------------------------------------------------------
#define ARP 72
#define ARPB (ARP*2)
#define QTILEB (128*ARPB)           // 18432 B per Q array
#define ATILE (64*ARPB)             // 9216 B per K/V array per buffer
#define ASTRIDE (2*ATILE)
#define ATTN_SMEM (2*QTILEB + 2*ASTRIDE)   // 73728 B

__global__ void __launch_bounds__(256, 2)
attn_mma(const float* __restrict__ amask)
{
    extern __shared__ __half dynsm[];

    const int tid  = threadIdx.x;
    const int wid  = tid >> 5;
    const int lane = tid & 31;
    const int qb = gridDim.x - 1 - blockIdx.x;   // long CTAs first
    const int h  = blockIdx.y;
    const int b  = blockIdx.z;
    const int q0 = qb * 128;
    const int qw = q0 + wid * 16;                // warp's 16 q-rows

    const size_t hoff = (size_t)(b*NH + h) * SEQ * HD;
    const __half* Qg  = g_Qh + hoff;
    const __half* Qlg = g_Ql + hoff;
    const __half* Kh  = g_Kh + hoff;
    const __half* Vh  = g_Vh + hoff;
    const float* am = amask + (size_t)b * SEQ;

    const int r  = lane >> 2;          // 0..7
    const int c2 = (lane & 3) << 1;    // 0,2,4,6

    const uint32_t sm0 = smem_u32(dynsm);
    const uint32_t bQh = sm0;
    const uint32_t bQl = sm0 + QTILEB;
    const uint32_t bKh = sm0 + 2*QTILEB;
    const uint32_t bVh = sm0 + 2*QTILEB + ASTRIDE;

    // lane addresses
    const uint32_t qa_off = (uint32_t)((wid*16 + (lane & 15)) * ARPB + (lane >> 4) * 16);
    uint32_t kb4_off[4];
#pragma unroll
    for (int jp = 0; jp < 4; jp++)
        kb4_off[jp] = (uint32_t)((jp*16 + (lane >> 4)*8 + (lane & 7)) * ARPB
                                 + ((lane >> 3) & 1) * 16);
    const uint32_t vt4 = (uint32_t)((lane & 15) * ARPB + (lane >> 4) * 16);

    float acc[8][4];
#pragma unroll
    for (int j = 0; j < 8; j++)
#pragma unroll
        for (int t = 0; t < 4; t++) acc[j][t] = 0.0f;
    float mrow0 = -3.0e38f, mrow1 = -3.0e38f, lrow0 = 0.0f, lrow1 = 0.0f;

    // K/V tile loaders: full 64x64, 2 x 16B per thread per array
    const int trow = tid >> 3;
    const int tcol = (tid & 7) << 3;
    const uint32_t tdst = (uint32_t)(trow * ARPB + tcol * 2);

    const int nkb = 2 * qb + 2;
    const int qr0 = qw + r, qr1 = qw + r + 8;

    // prologue: Q tile (once) + K/V tile 0 -> buf 0
    {
        const int qrow = tid >> 1;
        const int qcb  = (tid & 1) * 32;
        const uint32_t qd = (uint32_t)(qrow * ARPB + qcb * 2);
        const size_t qs = (size_t)(q0 + qrow) * HD + qcb;
#pragma unroll
        for (int c = 0; c < 4; c++) {
            cp_async16(bQh + qd + c*16, Qg  + qs + c*8);
            cp_async16(bQl + qd + c*16, Qlg + qs + c*8);
        }
#pragma unroll
        for (int it = 0; it < 2; it++) {
            const int rr = trow + it * 32;
            const size_t src = (size_t)rr * HD + tcol;
            const uint32_t dst = tdst + (uint32_t)(it * 32 * ARPB);
            cp_async16(bKh + dst, Kh + src);
            cp_async16(bVh + dst, Vh + src);
        }
        cp_commit();
    }

    for (int kb = 0; kb < nkb; kb++) {
        const int k0 = kb * 64;
        const uint32_t bo = (uint32_t)(kb & 1) * ATILE;
        cp_wait0();
        __syncthreads();
        if (kb + 1 < nkb) {
            const int kn = k0 + 64;
            const uint32_t bq = (uint32_t)((kb + 1) & 1) * ATILE;
#pragma unroll
            for (int it = 0; it < 2; it++) {
                const int rr = trow + it * 32;
                const size_t src = (size_t)(kn + rr) * HD + tcol;
                const uint32_t dst = bq + tdst + (uint32_t)(it * 32 * ARPB);
                cp_async16(bKh + dst, Kh + src);
                cp_async16(bVh + dst, Vh + src);
            }
            cp_commit();
        }

        // skip per-warp fully-masked tile (no-op).  Warp-uniform condition.
        if (qw + 15 < k0) continue;

        // S = (Qh+Ql) @ Kh^T  (2-product)
        float s[8][4];
#pragma unroll
        for (int j = 0; j < 8; j++)
#pragma unroll
            for (int t = 0; t < 4; t++) s[j][t] = 0.0f;
#pragma unroll
        for (int ds = 0; ds < 4; ds++) {
            uint32_t fqh[4], fql[4];
            ldm_x4(fqh, bQh + qa_off + ds * 32);
            ldm_x4(fql, bQl + qa_off + ds * 32);
#pragma unroll
            for (int jp = 0; jp < 4; jp++) {
                uint32_t fk[4];
                ldm_x4(fk, bKh + bo + kb4_off[jp] + ds * 32);
                mma_f16(s[2*jp],   fqh, fk + 0);
                mma_f16(s[2*jp+1], fqh, fk + 2);
                mma_f16(s[2*jp],   fql, fk + 0);
                mma_f16(s[2*jp+1], fql, fk + 2);
            }
        }

        // mask + online softmax (rows qr0, qr1)
        float rmax0 = -3.0e38f, rmax1 = -3.0e38f;
#pragma unroll
        for (int j = 0; j < 8; j++) {
            const int k = k0 + j*8 + c2;
            const float2 amv = *(const float2*)(am + k);
            s[j][0] = (k   <= qr0) ? s[j][0]*0.125f + amv.x : -10000.0f + amv.x;
            s[j][1] = (k+1 <= qr0) ? s[j][1]*0.125f + amv.y : -10000.0f + amv.y;
            s[j][2] = (k   <= qr1) ? s[j][2]*0.125f + amv.x : -10000.0f + amv.x;
            s[j][3] = (k+1 <= qr1) ? s[j][3]*0.125f + amv.y : -10000.0f + amv.y;
            rmax0 = fmaxf(rmax0, fmaxf(s[j][0], s[j][1]));
            rmax1 = fmaxf(rmax1, fmaxf(s[j][2], s[j][3]));
        }
        rmax0 = fmaxf(rmax0, __shfl_xor_sync(0xffffffffu, rmax0, 1));
        rmax0 = fmaxf(rmax0, __shfl_xor_sync(0xffffffffu, rmax0, 2));
        rmax1 = fmaxf(rmax1, __shfl_xor_sync(0xffffffffu, rmax1, 1));
        rmax1 = fmaxf(rmax1, __shfl_xor_sync(0xffffffffu, rmax1, 2));
        const float mnew0 = fmaxf(mrow0, rmax0);
        const float mnew1 = fmaxf(mrow1, rmax1);
        const float corr0 = __expf(mrow0 - mnew0);
        const float corr1 = __expf(mrow1 - mnew1);
        float rsum0 = 0.0f, rsum1 = 0.0f;
#pragma unroll
        for (int j = 0; j < 8; j++) {
            s[j][0] = __expf(s[j][0] - mnew0);
            s[j][1] = __expf(s[j][1] - mnew0);
            s[j][2] = __expf(s[j][2] - mnew1);
            s[j][3] = __expf(s[j][3] - mnew1);
            rsum0 += s[j][0] + s[j][1];
            rsum1 += s[j][2] + s[j][3];
        }
        rsum0 += __shfl_xor_sync(0xffffffffu, rsum0, 1);
        rsum0 += __shfl_xor_sync(0xffffffffu, rsum0, 2);
        rsum1 += __shfl_xor_sync(0xffffffffu, rsum1, 1);
        rsum1 += __shfl_xor_sync(0xffffffffu, rsum1, 2);
        lrow0 = lrow0 * corr0 + rsum0;
        lrow1 = lrow1 * corr1 + rsum1;
        mrow0 = mnew0; mrow1 = mnew1;
#pragma unroll
        for (int j = 0; j < 8; j++) {
            acc[j][0] *= corr0; acc[j][1] *= corr0;
            acc[j][2] *= corr1; acc[j][3] *= corr1;
        }

        // P fragments (register repack: A-frag t from S n-frags 2t, 2t+1)
        uint32_t fph[4][4], fpl[4][4];
#pragma unroll
        for (int t = 0; t < 4; t++) {
            split2(s[2*t][0],   s[2*t][1],   fph[t][0], fpl[t][0]);
            split2(s[2*t][2],   s[2*t][3],   fph[t][1], fpl[t][1]);
            split2(s[2*t+1][0], s[2*t+1][1], fph[t][2], fpl[t][2]);
            split2(s[2*t+1][2], s[2*t+1][3], fph[t][3], fpl[t][3]);
        }

        // O += (Ph+Pl) @ Vh  (2-product; V x4.trans)
#pragma unroll
        for (int t = 0; t < 4; t++) {
            const uint32_t ro = bo + vt4 + (uint32_t)(t * 16 * ARPB);
#pragma unroll
            for (int dnp = 0; dnp < 4; dnp++) {
                uint32_t fvh[4];
                ldm_x4t(fvh, bVh + ro + dnp * 32);
                mma_f16(acc[2*dnp],   fph[t], fvh + 0);
                mma_f16(acc[2*dnp+1], fph[t], fvh + 2);
                mma_f16(acc[2*dnp],   fpl[t], fvh + 0);
                mma_f16(acc[2*dnp+1], fpl[t], fvh + 2);
            }
        }
    }

    // epilogue: normalize, fp16 hi/lo split into g_Ah/g_Al at [b, q_view, h*64+d]
    const float inv0 = 1.0f / lrow0;
    const float inv1 = 1.0f / lrow1;
#pragma unroll
    for (int dn = 0; dn < 8; dn++) {
        const int d = dn*8 + c2;
        uint32_t hi0, lo0, hi1, lo1;
        split2(acc[dn][0]*inv0, acc[dn][1]*inv0, hi0, lo0);
        split2(acc[dn][2]*inv1, acc[dn][3]*inv1, hi1, lo1);
        const size_t i0 = ((size_t)b * SEQ + qr0) * NX + h * HD + d;
        const size_t i1 = ((size_t)b * SEQ + qr1) * NX + h * HD + d;
        *(uint32_t*)(g_Ah + i0) = hi0;
        *(uint32_t*)(g_Al + i0) = lo0;
        *(uint32_t*)(g_Ah + i1) = hi1;
        *(uint32_t*)(g_Al + i1) = lo1;
    }
}

// ---------------------------------------------------------------------------
extern "C" void kernel_launch(void* const* d_in, const int* in_sizes, int n_in,
                              void* d_out, int out_size)
{
    const float* hidden = (const float*)d_in[0];
    const float* amask  = (const float*)d_in[1];
    const float* w_attn = (const float*)d_in[2];
    const float* b_attn = (const float*)d_in[3];
    const float* w_proj = (const float*)d_in[4];
    const float* b_proj = (const float*)d_in[5];
    float* out = (float*)d_out;

    // Host-side attribute set: not a stream op, graph-capture-safe, idempotent.
    cudaFuncSetAttribute(attn_mma, cudaFuncAttributeMaxDynamicSharedMemorySize,
                         ATTN_SMEM);

    __half *Bh1, *Bh2, *Ah, *Al;
    cudaGetSymbolAddress((void**)&Bh1, g_Bh1);
    cudaGetSymbolAddress((void**)&Bh2, g_Bh2);
    cudaGetSymbolAddress((void**)&Ah,  g_Ah);
    cudaGetSymbolAddress((void**)&Al,  g_Al);

    // Pre-pass: transpose weights (hi only), split activations
    wsplitT<<<dim3(NQKV/32, NX/32), 256>>>(w_attn, Bh1, NX, NQKV);
    wsplitT<<<dim3(NX/32,   NX/32), 256>>>(w_proj, Bh2, NX, NX);
    asplit<<<(MROWS*NX)/(256*4), 256>>>(hidden, Ah, Al);

    // 1) QKV = X @ W_attn + b -> fp16 Q(hi/lo)/K/V, quirky per-head layout
    mma_gemm_impl<<<dim3(NQKV/128, MROWS/128), 256>>>(
        Ah, Al, Bh1, b_attn, nullptr, NQKV, NX, 1);

    // 2) HMMA flash attention -> fp16 hi/lo activations
    attn_mma<<<dim3(SEQ/128, NH, BSZ), 256, ATTN_SMEM>>>(amask);

    // 3) out = A @ W_proj + b
    mma_gemm_impl<<<dim3(NX/128, MROWS/128), 256>>>(
        Ah, Al, Bh2, b_proj, out, NX, NX, 0);
}